// round 14
// baseline (speedup 1.0000x reference)
#include <cuda_runtime.h>
#include <cuda_bf16.h>
#include <cstdint>

#define BB    8
#define SS    2048
#define DIN   2048
#define DOUT  2048
#define KK    16
#define RR    16

// Pre-split bf16 hi/lo mixed weights (u32 = packed bf16 pair over last dim),
// plus K-quarter z partials.
__device__ __align__(16) uint32_t g_Amh[BB * RR * DIN / 2];    // [b][r][i/2]
__device__ __align__(16) uint32_t g_Aml[BB * RR * DIN / 2];
__device__ __align__(16) uint32_t g_BmTh[BB * DOUT * RR / 2];  // [b][o][r/2]
__device__ __align__(16) uint32_t g_BmTl[BB * DOUT * RR / 2];
__device__ __align__(16) float    g_zp[4 * BB * SS * RR];      // [kq][b][s][r]

// z smem layout (u32 words):
//   buf0 h: hi[4608] lo[4608]   buf1 h: hi[4608] lo[4608]   Am[10240]
#define ZB_HSLO  4608
#define ZB_SIZE  9216                     // one h buffer (hi+lo)
#define ZB_AM    (2 * ZB_SIZE)            // 18432
#define Z_WORDS  (2 * ZB_SIZE + 10240)    // 28672
#define Z_SMEM_BYTES (Z_WORDS * 4)        // 114688

// ---------------------------------------------------------------------------
__device__ __forceinline__ void split2(float x, float y, uint32_t &hi, uint32_t &lo) {
    __nv_bfloat162 h2 = __floats2bfloat162_rn(x, y);
    float rx = x - __bfloat162float(h2.x);
    float ry = y - __bfloat162float(h2.y);
    __nv_bfloat162 l2 = __floats2bfloat162_rn(rx, ry);
    hi = *reinterpret_cast<uint32_t*>(&h2);
    lo = *reinterpret_cast<uint32_t*>(&l2);
}

__device__ __forceinline__ void pack4(float4 v, uint2 &hi, uint2 &lo) {
    split2(v.x, v.y, hi.x, lo.x);
    split2(v.z, v.w, hi.y, lo.y);
}

// m16n8k16 bf16 mma, fp32 accumulate.
__device__ __forceinline__ void mma16(float* d,
                                      uint32_t a0, uint32_t a1, uint32_t a2, uint32_t a3,
                                      uint32_t b0, uint32_t b1) {
    asm("mma.sync.aligned.m16n8k16.row.col.f32.bf16.bf16.f32 "
        "{%0,%1,%2,%3}, {%4,%5,%6,%7}, {%8,%9}, {%0,%1,%2,%3};"
        : "+f"(d[0]), "+f"(d[1]), "+f"(d[2]), "+f"(d[3])
        : "r"(a0), "r"(a1), "r"(a2), "r"(a3), "r"(b0), "r"(b1));
}

// ---------------------------------------------------------------------------
// Kernel 1: mix banks -> pre-split bf16 hi/lo (coalesced B part). Unchanged.
// ---------------------------------------------------------------------------
__global__ void __launch_bounds__(256, 2) mix_kernel(const float* __restrict__ alpha,
                                                     const float* __restrict__ Abank,
                                                     const float* __restrict__ Bbank) {
    __shared__ float sal[BB * KK];
    if (threadIdx.x < BB * KK) sal[threadIdx.x] = alpha[threadIdx.x];
    __syncthreads();

    int t = blockIdx.x * blockDim.x + threadIdx.x;
    if (t < 32768) {
        int bg  = t >> 13;
        int rem = t & 8191;
        int r   = rem >> 9;
        int i   = (rem & 511) << 2;
        const float* ab = Abank + (size_t)r * DIN + i;
        float4 a0 = make_float4(0.f, 0.f, 0.f, 0.f);
        float4 a1 = a0;
#pragma unroll
        for (int k = 0; k < KK; k++) {
            float4 v = *(const float4*)(ab + (size_t)k * RR * DIN);
            float c0 = sal[(2 * bg) * KK + k];
            float c1 = sal[(2 * bg + 1) * KK + k];
            a0.x += c0 * v.x; a0.y += c0 * v.y; a0.z += c0 * v.z; a0.w += c0 * v.w;
            a1.x += c1 * v.x; a1.y += c1 * v.y; a1.z += c1 * v.z; a1.w += c1 * v.w;
        }
        uint2 hi, lo;
        size_t idx0 = (size_t)((2 * bg) * RR + r) * (DIN / 2) + (i >> 1);
        pack4(a0, hi, lo);
        *(uint2*)&g_Amh[idx0] = hi;  *(uint2*)&g_Aml[idx0] = lo;
        size_t idx1 = (size_t)((2 * bg + 1) * RR + r) * (DIN / 2) + (i >> 1);
        pack4(a1, hi, lo);
        *(uint2*)&g_Amh[idx1] = hi;  *(uint2*)&g_Aml[idx1] = lo;
    } else {
        int t2  = t - 32768;
        int bg  = t2 >> 13;
        int rem = t2 & 8191;
        int o   = rem >> 2;
        int q   = rem & 3;
        const float* bb = Bbank + (size_t)o * RR + 4 * q;
        float4 a0 = make_float4(0.f, 0.f, 0.f, 0.f);
        float4 a1 = a0;
#pragma unroll
        for (int k = 0; k < KK; k++) {
            float4 v = *(const float4*)(bb + (size_t)k * DOUT * RR);
            float c0 = sal[(2 * bg) * KK + k];
            float c1 = sal[(2 * bg + 1) * KK + k];
            a0.x += c0 * v.x; a0.y += c0 * v.y; a0.z += c0 * v.z; a0.w += c0 * v.w;
            a1.x += c1 * v.x; a1.y += c1 * v.y; a1.z += c1 * v.z; a1.w += c1 * v.w;
        }
        uint2 hi, lo;
        size_t idx0 = (size_t)((2 * bg) * DOUT + o) * (RR / 2) + 2 * q;
        pack4(a0, hi, lo);
        *(uint2*)&g_BmTh[idx0] = hi;  *(uint2*)&g_BmTl[idx0] = lo;
        size_t idx1 = (size_t)((2 * bg + 1) * DOUT + o) * (RR / 2) + 2 * q;
        pack4(a1, hi, lo);
        *(uint2*)&g_BmTh[idx1] = hi;  *(uint2*)&g_BmTl[idx1] = lo;
    }
}

// ---------------------------------------------------------------------------
// Kernel 2: z partials. K split in QUARTERS; Am slice staged ONCE per CTA.
//   g_zp[kq][b][s][r] = sum_{i in quarter} Am[b,r,i] * h[b,s,i]
// Grid 512 = kq(4) x st(16, 128 s) x b(8); 256 thr = 8 warps x 16 s.
// smem: double-buffered h (hi/lo, pitch 36) + Am slice (256 ic x [hi16|lo16],
// pitch 40 -> conflict-free A-frag reads: bank = 8*tig + gid).
// Chunk loop: stage h(c+1), prefetch h(c+2), compute(c); one sync per chunk.
// ---------------------------------------------------------------------------
__global__ void __launch_bounds__(256, 2) z_mma_kernel(const float* __restrict__ h) {
    extern __shared__ uint32_t zsm[];
    uint32_t* const buf0 = zsm;
    uint32_t* const buf1 = zsm + ZB_SIZE;
    uint32_t* const am   = zsm + ZB_AM;     // [ic][0..15]=hi, [16..31]=lo, pitch 40

    int kq = blockIdx.x & 3;
    int st = (blockIdx.x >> 2) & 15;
    int b  = blockIdx.x >> 6;
    int s0 = st * 128;
    int icb = kq * 256;              // u32-column base of this K-quarter

    int tid  = threadIdx.x;
    int w    = tid >> 5;
    int lane = tid & 31;
    int gid  = lane >> 2;
    int tig  = lane & 3;

    int row16 = tid >> 4;
    int col   = tid & 15;

    const uint32_t* amh = g_Amh + (size_t)b * RR * (DIN / 2);
    const uint32_t* aml = g_Aml + (size_t)b * RR * (DIN / 2);
    const float*    hb  = h + (size_t)(b * SS + s0 + row16) * DIN + col * 4;

    // ---- stage Am slice once: 256 ic x 16 r, hi+lo (coalesced gmem reads) ----
    {
        int r  = tid >> 8;   // unused split helper; do 16 iters of (r, ic)
#pragma unroll
        for (int j = 0; j < 16; j++) {
            int idx = j * 256 + tid;        // 0..4095
            int rr  = idx >> 8;             // 0..15
            int ic  = idx & 255;            // 0..255 (lanes consecutive -> coalesced)
            size_t g = (size_t)rr * (DIN / 2) + icb + ic;
            am[ic * 40 + rr]      = amh[g];
            am[ic * 40 + 16 + rr] = aml[g];
        }
        (void)r;
    }

    float d[2][4];
#pragma unroll
    for (int nt = 0; nt < 2; nt++)
#pragma unroll
        for (int j = 0; j < 4; j++) d[nt][j] = 0.f;

    float4 v[8];

    // ---- load h chunk 0 regs & stage -> buf0 ----
#pragma unroll
    for (int p = 0; p < 8; p++)
        v[p] = *(const float4*)(hb + (size_t)(p * 16) * DIN + 2 * icb);
    {
        uint32_t* hsh = buf0;
        uint32_t* hsl = buf0 + ZB_HSLO;
#pragma unroll
        for (int p = 0; p < 8; p++) {
            uint32_t h01, l01, h23, l23;
            split2(v[p].x, v[p].y, h01, l01);
            split2(v[p].z, v[p].w, h23, l23);
            int base = (p * 16 + row16) * 36 + col * 2;
            hsh[base] = h01;  hsh[base + 1] = h23;
            hsl[base] = l01;  hsl[base + 1] = l23;
        }
    }
    __syncthreads();

    // ---- prefetch h chunk 1 ----
#pragma unroll
    for (int p = 0; p < 8; p++)
        v[p] = *(const float4*)(hb + (size_t)(p * 16) * DIN + 2 * (icb + 32));

#pragma unroll 1
    for (int c = 0; c < 8; c++) {
        uint32_t* cur = (c & 1) ? buf1 : buf0;
        uint32_t* nxt = (c & 1) ? buf0 : buf1;

        // ---- stage h chunk c+1 into nxt ----
        if (c < 7) {
            uint32_t* hsh = nxt;
            uint32_t* hsl = nxt + ZB_HSLO;
#pragma unroll
            for (int p = 0; p < 8; p++) {
                uint32_t h01, l01, h23, l23;
                split2(v[p].x, v[p].y, h01, l01);
                split2(v[p].z, v[p].w, h23, l23);
                int base = (p * 16 + row16) * 36 + col * 2;
                hsh[base] = h01;  hsh[base + 1] = h23;
                hsl[base] = l01;  hsl[base + 1] = l23;
            }
        }

        // ---- prefetch h chunk c+2 ----
        if (c < 6) {
            int icn = icb + (c + 2) * 32;
#pragma unroll
            for (int p = 0; p < 8; p++)
                v[p] = *(const float4*)(hb + (size_t)(p * 16) * DIN + 2 * icn);
        }

        // ---- compute chunk c: 4 k16 steps, A from Am smem, B from cur ----
        {
            const uint32_t* hsh = cur;
            const uint32_t* hsl = cur + ZB_HSLO;
            int ico = c * 32;
#pragma unroll
            for (int km = 0; km < 4; km++) {
                int ac0 = (ico + km * 8 + tig) * 40;
                int ac1 = (ico + km * 8 + 4 + tig) * 40;
                uint32_t Ah0 = am[ac0 + gid],      Ah1 = am[ac0 + gid + 8];
                uint32_t Ah2 = am[ac1 + gid],      Ah3 = am[ac1 + gid + 8];
                uint32_t Al0 = am[ac0 + 16 + gid], Al1 = am[ac0 + 24 + gid];
                uint32_t Al2 = am[ac1 + 16 + gid], Al3 = am[ac1 + 24 + gid];
#pragma unroll
                for (int nt = 0; nt < 2; nt++) {
                    int srow = (w * 16 + nt * 8 + gid) * 36 + km * 8 + tig;
                    uint32_t Bh0 = hsh[srow], Bh1 = hsh[srow + 4];
                    uint32_t Bl0 = hsl[srow], Bl1 = hsl[srow + 4];
                    mma16(d[nt], Ah0, Ah1, Ah2, Ah3, Bh0, Bh1);
                    mma16(d[nt], Ah0, Ah1, Ah2, Ah3, Bl0, Bl1);
                    mma16(d[nt], Al0, Al1, Al2, Al3, Bh0, Bh1);
                }
            }
        }
        __syncthreads();
    }

    // Epilogue: D rows = r (gid, gid+8), cols = s (2tig, 2tig+1).
    float* zp = g_zp + ((size_t)(kq * BB + b) * SS) * RR;
#pragma unroll
    for (int nt = 0; nt < 2; nt++) {
        int sbase = s0 + w * 16 + nt * 8 + 2 * tig;
        zp[(size_t)sbase * RR + gid]           = d[nt][0];
        zp[(size_t)(sbase + 1) * RR + gid]     = d[nt][1];
        zp[(size_t)sbase * RR + gid + 8]       = d[nt][2];
        zp[(size_t)(sbase + 1) * RR + gid + 8] = d[nt][3];
    }
}

// ---------------------------------------------------------------------------
// Kernel 3: delta[b][s][o] = sum_r z[b][s][r] * BmT[b][o][r]
// m16n8k16: 3 mma per 16x8 tile. Sums 4 K-quarter partials at staging.
// ---------------------------------------------------------------------------
__global__ void __launch_bounds__(512, 2) delta_kernel(float* __restrict__ out) {
    __shared__ float zs[128 * 20];
    __shared__ uint32_t bsh[128 * 9];
    __shared__ uint32_t bsl[128 * 9];

    int ot = blockIdx.x & 15;
    int st = (blockIdx.x >> 4) & 15;
    int b  = blockIdx.x >> 8;
    int s0 = st * 128;
    int o0 = ot * 128;
    int tid = threadIdx.x;

    {
        int row = tid >> 2;
        int col = (tid & 3) << 2;
        size_t src = ((size_t)(b * SS) + s0 + row) * RR + col;
        const size_t QS = (size_t)BB * SS * RR;
        float4 p0 = *(const float4*)(g_zp + src);
        float4 p1 = *(const float4*)(g_zp + QS + src);
        float4 p2 = *(const float4*)(g_zp + 2 * QS + src);
        float4 p3 = *(const float4*)(g_zp + 3 * QS + src);
        *(float4*)(zs + row * 20 + col) =
            make_float4(p0.x + p1.x + p2.x + p3.x,
                        p0.y + p1.y + p2.y + p3.y,
                        p0.z + p1.z + p2.z + p3.z,
                        p0.w + p1.w + p2.w + p3.w);
    }
    {
        size_t base = (size_t)(b * DOUT + o0) * (RR / 2);
#pragma unroll
        for (int j = 0; j < 2; j++) {
            int idx = tid * 2 + j;
            int row = idx >> 3;
            int col = idx & 7;
            bsh[row * 9 + col] = g_BmTh[base + idx];
            bsl[row * 9 + col] = g_BmTl[base + idx];
        }
    }
    __syncthreads();

    int w = tid >> 5;
    int lane = tid & 31;
    int gid = lane >> 2;
    int tig = lane & 3;
    int sw = (w & 7) * 16;
    int ow = (w >> 3) * 64;

    uint32_t Ah[4], Al[4];
#pragma unroll
    for (int kk = 0; kk < 2; kk++) {
        float2 v0 = *(const float2*)(zs + (sw + gid) * 20 + kk * 8 + tig * 2);
        float2 v1 = *(const float2*)(zs + (sw + gid + 8) * 20 + kk * 8 + tig * 2);
        split2(v0.x, v0.y, Ah[2 * kk],     Al[2 * kk]);
        split2(v1.x, v1.y, Ah[2 * kk + 1], Al[2 * kk + 1]);
    }

#pragma unroll
    for (int nt = 0; nt < 8; nt++) {
        int brow = (ow + nt * 8 + gid) * 9;
        uint32_t Bh0 = bsh[brow + tig];
        uint32_t Bh1 = bsh[brow + 4 + tig];
        uint32_t Bl0 = bsl[brow + tig];
        uint32_t Bl1 = bsl[brow + 4 + tig];

        float d[4] = {0.f, 0.f, 0.f, 0.f};
        mma16(d, Ah[0], Ah[1], Ah[2], Ah[3], Bh0, Bh1);
        mma16(d, Ah[0], Ah[1], Ah[2], Ah[3], Bl0, Bl1);
        mma16(d, Al[0], Al[1], Al[2], Al[3], Bh0, Bh1);

        float* op = out + ((size_t)(b * SS + s0 + sw + gid)) * DOUT
                        + o0 + ow + nt * 8 + tig * 2;
        *(float2*)op = make_float2(d[0], d[1]);
        *(float2*)(op + (size_t)8 * DOUT) = make_float2(d[2], d[3]);
    }
}

// ---------------------------------------------------------------------------
extern "C" void kernel_launch(void* const* d_in, const int* in_sizes, int n_in,
                              void* d_out, int out_size) {
    const float* h     = (const float*)d_in[0];   // [8,2048,2048]
    const float* alpha = (const float*)d_in[1];   // [8,16]
    const float* Abank = (const float*)d_in[2];   // [16,16,2048]
    const float* Bbank = (const float*)d_in[3];   // [16,2048,16]
    float* out = (float*)d_out;                   // [8,2048,2048]

    static bool attr_set = false;
    if (!attr_set) {
        cudaFuncSetAttribute(z_mma_kernel,
                             cudaFuncAttributeMaxDynamicSharedMemorySize,
                             Z_SMEM_BYTES);
        attr_set = true;
    }

    mix_kernel<<<256, 256>>>(alpha, Abank, Bbank);
    z_mma_kernel<<<512, 256, Z_SMEM_BYTES>>>(h);
    delta_kernel<<<2048, 512>>>(out);
}

// round 15
// speedup vs baseline: 1.1988x; 1.1988x over previous
#include <cuda_runtime.h>
#include <cuda_bf16.h>
#include <cstdint>

#define BB    8
#define SS    2048
#define DIN   2048
#define DOUT  2048
#define KK    16
#define RR    16

// Pre-split bf16 hi/lo mixed weights (u32 = packed bf16 pair over last dim),
// plus K-split z partials.
__device__ __align__(16) uint32_t g_Amh[BB * RR * DIN / 2];    // [b][r][i/2]
__device__ __align__(16) uint32_t g_Aml[BB * RR * DIN / 2];
__device__ __align__(16) uint32_t g_BmTh[BB * DOUT * RR / 2];  // [b][o][r/2]
__device__ __align__(16) uint32_t g_BmTl[BB * DOUT * RR / 2];
__device__ __align__(16) float    g_zp[2 * BB * SS * RR];      // [kh][b][s][r]

// z smem buffer layout (u32 words): hs_hi[4608] hs_lo[4608] as_hi[768] as_lo[768]
#define ZB_HSLO 4608
#define ZB_ASHI 9216
#define ZB_ASLO 9984
#define ZB_SIZE 10752            // words per buffer
#define Z_SMEM_BYTES (2 * ZB_SIZE * 4)   // 86016 -> occ 2 (172 KB < 228 KB)

// ---------------------------------------------------------------------------
__device__ __forceinline__ void split2(float x, float y, uint32_t &hi, uint32_t &lo) {
    __nv_bfloat162 h2 = __floats2bfloat162_rn(x, y);
    float rx = x - __bfloat162float(h2.x);
    float ry = y - __bfloat162float(h2.y);
    __nv_bfloat162 l2 = __floats2bfloat162_rn(rx, ry);
    hi = *reinterpret_cast<uint32_t*>(&h2);
    lo = *reinterpret_cast<uint32_t*>(&l2);
}

__device__ __forceinline__ void pack4(float4 v, uint2 &hi, uint2 &lo) {
    split2(v.x, v.y, hi.x, lo.x);
    split2(v.z, v.w, hi.y, lo.y);
}

// m16n8k16 bf16 mma, fp32 accumulate.
__device__ __forceinline__ void mma16(float* d,
                                      uint32_t a0, uint32_t a1, uint32_t a2, uint32_t a3,
                                      uint32_t b0, uint32_t b1) {
    asm("mma.sync.aligned.m16n8k16.row.col.f32.bf16.bf16.f32 "
        "{%0,%1,%2,%3}, {%4,%5,%6,%7}, {%8,%9}, {%0,%1,%2,%3};"
        : "+f"(d[0]), "+f"(d[1]), "+f"(d[2]), "+f"(d[3])
        : "r"(a0), "r"(a1), "r"(a2), "r"(a3), "r"(b0), "r"(b1));
}

// ---------------------------------------------------------------------------
// Kernel 1: mix banks -> pre-split bf16 hi/lo (coalesced B part). Unchanged.
// ---------------------------------------------------------------------------
__global__ void __launch_bounds__(256, 2) mix_kernel(const float* __restrict__ alpha,
                                                     const float* __restrict__ Abank,
                                                     const float* __restrict__ Bbank) {
    __shared__ float sal[BB * KK];
    if (threadIdx.x < BB * KK) sal[threadIdx.x] = alpha[threadIdx.x];
    __syncthreads();

    int t = blockIdx.x * blockDim.x + threadIdx.x;
    if (t < 32768) {
        int bg  = t >> 13;
        int rem = t & 8191;
        int r   = rem >> 9;
        int i   = (rem & 511) << 2;
        const float* ab = Abank + (size_t)r * DIN + i;
        float4 a0 = make_float4(0.f, 0.f, 0.f, 0.f);
        float4 a1 = a0;
#pragma unroll
        for (int k = 0; k < KK; k++) {
            float4 v = *(const float4*)(ab + (size_t)k * RR * DIN);
            float c0 = sal[(2 * bg) * KK + k];
            float c1 = sal[(2 * bg + 1) * KK + k];
            a0.x += c0 * v.x; a0.y += c0 * v.y; a0.z += c0 * v.z; a0.w += c0 * v.w;
            a1.x += c1 * v.x; a1.y += c1 * v.y; a1.z += c1 * v.z; a1.w += c1 * v.w;
        }
        uint2 hi, lo;
        size_t idx0 = (size_t)((2 * bg) * RR + r) * (DIN / 2) + (i >> 1);
        pack4(a0, hi, lo);
        *(uint2*)&g_Amh[idx0] = hi;  *(uint2*)&g_Aml[idx0] = lo;
        size_t idx1 = (size_t)((2 * bg + 1) * RR + r) * (DIN / 2) + (i >> 1);
        pack4(a1, hi, lo);
        *(uint2*)&g_Amh[idx1] = hi;  *(uint2*)&g_Aml[idx1] = lo;
    } else {
        int t2  = t - 32768;
        int bg  = t2 >> 13;
        int rem = t2 & 8191;
        int o   = rem >> 2;
        int q   = rem & 3;
        const float* bb = Bbank + (size_t)o * RR + 4 * q;
        float4 a0 = make_float4(0.f, 0.f, 0.f, 0.f);
        float4 a1 = a0;
#pragma unroll
        for (int k = 0; k < KK; k++) {
            float4 v = *(const float4*)(bb + (size_t)k * DOUT * RR);
            float c0 = sal[(2 * bg) * KK + k];
            float c1 = sal[(2 * bg + 1) * KK + k];
            a0.x += c0 * v.x; a0.y += c0 * v.y; a0.z += c0 * v.z; a0.w += c0 * v.w;
            a1.x += c1 * v.x; a1.y += c1 * v.y; a1.z += c1 * v.z; a1.w += c1 * v.w;
        }
        uint2 hi, lo;
        size_t idx0 = (size_t)((2 * bg) * DOUT + o) * (RR / 2) + 2 * q;
        pack4(a0, hi, lo);
        *(uint2*)&g_BmTh[idx0] = hi;  *(uint2*)&g_BmTl[idx0] = lo;
        size_t idx1 = (size_t)((2 * bg + 1) * DOUT + o) * (RR / 2) + 2 * q;
        pack4(a1, hi, lo);
        *(uint2*)&g_BmTh[idx1] = hi;  *(uint2*)&g_BmTl[idx1] = lo;
    }
}

// ---------------------------------------------------------------------------
// Kernel 2: z partials, DOUBLE-BUFFERED pipeline (R13 base).
//   g_zp[kh][b][s][r] = sum_{i in half} Am[b,r,i] * h[b,s,i]
// Grid 256 = kh(2) x st(16, 128 s) x b(8); 256 thr = 8 warps x 16 s.
// CHANGE vs R13: Am chunk gather is COALESCED — warp w loads the 32
// consecutive u32 of rows r = w and w+8 (128B requests, zero replay),
// instead of each thread striding 4KB across r.
// ---------------------------------------------------------------------------
__global__ void __launch_bounds__(256, 2) z_mma_kernel(const float* __restrict__ h) {
    extern __shared__ uint32_t zsm[];
    uint32_t* const buf0 = zsm;
    uint32_t* const buf1 = zsm + ZB_SIZE;

    int kh = blockIdx.x & 1;
    int st = (blockIdx.x >> 1) & 15;
    int b  = blockIdx.x >> 5;
    int s0 = st * 128;
    int ibase = kh * (DIN / 4);   // u32 columns per K-half = 512

    int tid  = threadIdx.x;
    int w    = tid >> 5;
    int lane = tid & 31;
    int gid  = lane >> 2;
    int tig  = lane & 3;

    int row16 = tid >> 4;
    int col   = tid & 15;

    const uint32_t* amh = g_Amh + (size_t)b * RR * (DIN / 2);
    const uint32_t* aml = g_Aml + (size_t)b * RR * (DIN / 2);
    const float*    hb  = h + (size_t)(b * SS + s0 + row16) * DIN + col * 4;

    float d[2][4];
#pragma unroll
    for (int nt = 0; nt < 2; nt++)
#pragma unroll
        for (int j = 0; j < 4; j++) d[nt][j] = 0.f;

    float4 v[8];
    uint32_t ar_hi[2], ar_lo[2];

    // ---- load chunk 0 regs (coalesced Am gather: warp per r-row) ----
    {
        int icol0 = ibase;
#pragma unroll
        for (int p = 0; p < 8; p++)
            v[p] = *(const float4*)(hb + (size_t)(p * 16) * DIN + 2 * icol0);
#pragma unroll
        for (int p = 0; p < 2; p++) {
            size_t gidx = (size_t)(w + 8 * p) * (DIN / 2) + icol0 + lane;
            ar_hi[p] = amh[gidx];
            ar_lo[p] = aml[gidx];
        }
    }
    // ---- stage chunk 0 -> buf0 ----
    {
        uint32_t* hsh = buf0;
        uint32_t* hsl = buf0 + ZB_HSLO;
#pragma unroll
        for (int p = 0; p < 8; p++) {
            uint32_t h01, l01, h23, l23;
            split2(v[p].x, v[p].y, h01, l01);
            split2(v[p].z, v[p].w, h23, l23);
            int base = (p * 16 + row16) * 36 + col * 2;
            hsh[base] = h01;  hsh[base + 1] = h23;
            hsl[base] = l01;  hsl[base + 1] = l23;
        }
        uint32_t* ash = buf0 + ZB_ASHI;
        uint32_t* asl = buf0 + ZB_ASLO;
#pragma unroll
        for (int p = 0; p < 2; p++) {
            ash[lane * 24 + (w + 8 * p)] = ar_hi[p];
            asl[lane * 24 + (w + 8 * p)] = ar_lo[p];
        }
    }
    __syncthreads();

    // ---- prefetch chunk 1 regs ----
    {
        int icol1 = ibase + 32;
#pragma unroll
        for (int p = 0; p < 8; p++)
            v[p] = *(const float4*)(hb + (size_t)(p * 16) * DIN + 2 * icol1);
#pragma unroll
        for (int p = 0; p < 2; p++) {
            size_t gidx = (size_t)(w + 8 * p) * (DIN / 2) + icol1 + lane;
            ar_hi[p] = amh[gidx];
            ar_lo[p] = aml[gidx];
        }
    }

#pragma unroll 1
    for (int c = 0; c < 16; c++) {
        uint32_t* cur = (c & 1) ? buf1 : buf0;
        uint32_t* nxt = (c & 1) ? buf0 : buf1;

        // ---- stage chunk c+1 into nxt (regs already loaded) ----
        if (c < 15) {
            uint32_t* hsh = nxt;
            uint32_t* hsl = nxt + ZB_HSLO;
#pragma unroll
            for (int p = 0; p < 8; p++) {
                uint32_t h01, l01, h23, l23;
                split2(v[p].x, v[p].y, h01, l01);
                split2(v[p].z, v[p].w, h23, l23);
                int base = (p * 16 + row16) * 36 + col * 2;
                hsh[base] = h01;  hsh[base + 1] = h23;
                hsl[base] = l01;  hsl[base + 1] = l23;
            }
            uint32_t* ash = nxt + ZB_ASHI;
            uint32_t* asl = nxt + ZB_ASLO;
#pragma unroll
            for (int p = 0; p < 2; p++) {
                ash[lane * 24 + (w + 8 * p)] = ar_hi[p];
                asl[lane * 24 + (w + 8 * p)] = ar_lo[p];
            }
        }

        // ---- prefetch chunk c+2 regs (v dead after staging) ----
        if (c < 14) {
            int icoln = ibase + (c + 2) * 32;
#pragma unroll
            for (int p = 0; p < 8; p++)
                v[p] = *(const float4*)(hb + (size_t)(p * 16) * DIN + 2 * icoln);
#pragma unroll
            for (int p = 0; p < 2; p++) {
                size_t gidx = (size_t)(w + 8 * p) * (DIN / 2) + icoln + lane;
                ar_hi[p] = amh[gidx];
                ar_lo[p] = aml[gidx];
            }
        }

        // ---- compute chunk c from cur: 4 k16 steps ----
        {
            const uint32_t* hsh = cur;
            const uint32_t* hsl = cur + ZB_HSLO;
            const uint32_t* ash = cur + ZB_ASHI;
            const uint32_t* asl = cur + ZB_ASLO;
#pragma unroll
            for (int km = 0; km < 4; km++) {
                int ac0 = (km * 8 + tig) * 24;
                int ac1 = (km * 8 + 4 + tig) * 24;
                uint32_t Ah0 = ash[ac0 + gid], Ah1 = ash[ac0 + gid + 8];
                uint32_t Ah2 = ash[ac1 + gid], Ah3 = ash[ac1 + gid + 8];
                uint32_t Al0 = asl[ac0 + gid], Al1 = asl[ac0 + gid + 8];
                uint32_t Al2 = asl[ac1 + gid], Al3 = asl[ac1 + gid + 8];
#pragma unroll
                for (int nt = 0; nt < 2; nt++) {
                    int srow = (w * 16 + nt * 8 + gid) * 36 + km * 8 + tig;
                    uint32_t Bh0 = hsh[srow], Bh1 = hsh[srow + 4];
                    uint32_t Bl0 = hsl[srow], Bl1 = hsl[srow + 4];
                    mma16(d[nt], Ah0, Ah1, Ah2, Ah3, Bh0, Bh1);
                    mma16(d[nt], Ah0, Ah1, Ah2, Ah3, Bl0, Bl1);
                    mma16(d[nt], Al0, Al1, Al2, Al3, Bh0, Bh1);
                }
            }
        }
        __syncthreads();   // nxt fully staged; cur free for re-staging
    }

    // Epilogue: D rows = r (gid, gid+8), cols = s (2tig, 2tig+1).
    float* zp = g_zp + ((size_t)(kh * BB + b) * SS) * RR;
#pragma unroll
    for (int nt = 0; nt < 2; nt++) {
        int sbase = s0 + w * 16 + nt * 8 + 2 * tig;
        zp[(size_t)sbase * RR + gid]           = d[nt][0];
        zp[(size_t)(sbase + 1) * RR + gid]     = d[nt][1];
        zp[(size_t)sbase * RR + gid + 8]       = d[nt][2];
        zp[(size_t)(sbase + 1) * RR + gid + 8] = d[nt][3];
    }
}

// ---------------------------------------------------------------------------
// Kernel 3: delta[b][s][o] = sum_r z[b][s][r] * BmT[b][o][r]
// m16n8k16: 3 mma per 16x8 tile. Unchanged (at its floor). 2048 CTAs, 512 thr.
// ---------------------------------------------------------------------------
__global__ void __launch_bounds__(512, 2) delta_kernel(float* __restrict__ out) {
    __shared__ float zs[128 * 20];
    __shared__ uint32_t bsh[128 * 9];
    __shared__ uint32_t bsl[128 * 9];

    int ot = blockIdx.x & 15;
    int st = (blockIdx.x >> 4) & 15;
    int b  = blockIdx.x >> 8;
    int s0 = st * 128;
    int o0 = ot * 128;
    int tid = threadIdx.x;

    {
        int row = tid >> 2;
        int col = (tid & 3) << 2;
        size_t src = ((size_t)(b * SS) + s0 + row) * RR + col;
        float4 p0 = *(const float4*)(g_zp + src);
        float4 p1 = *(const float4*)(g_zp + (size_t)BB * SS * RR + src);
        *(float4*)(zs + row * 20 + col) =
            make_float4(p0.x + p1.x, p0.y + p1.y, p0.z + p1.z, p0.w + p1.w);
    }
    {
        size_t base = (size_t)(b * DOUT + o0) * (RR / 2);
#pragma unroll
        for (int j = 0; j < 2; j++) {
            int idx = tid * 2 + j;
            int row = idx >> 3;
            int col = idx & 7;
            bsh[row * 9 + col] = g_BmTh[base + idx];
            bsl[row * 9 + col] = g_BmTl[base + idx];
        }
    }
    __syncthreads();

    int w = tid >> 5;
    int lane = tid & 31;
    int gid = lane >> 2;
    int tig = lane & 3;
    int sw = (w & 7) * 16;
    int ow = (w >> 3) * 64;

    uint32_t Ah[4], Al[4];
#pragma unroll
    for (int kk = 0; kk < 2; kk++) {
        float2 v0 = *(const float2*)(zs + (sw + gid) * 20 + kk * 8 + tig * 2);
        float2 v1 = *(const float2*)(zs + (sw + gid + 8) * 20 + kk * 8 + tig * 2);
        split2(v0.x, v0.y, Ah[2 * kk],     Al[2 * kk]);
        split2(v1.x, v1.y, Ah[2 * kk + 1], Al[2 * kk + 1]);
    }

#pragma unroll
    for (int nt = 0; nt < 8; nt++) {
        int brow = (ow + nt * 8 + gid) * 9;
        uint32_t Bh0 = bsh[brow + tig];
        uint32_t Bh1 = bsh[brow + 4 + tig];
        uint32_t Bl0 = bsl[brow + tig];
        uint32_t Bl1 = bsl[brow + 4 + tig];

        float d[4] = {0.f, 0.f, 0.f, 0.f};
        mma16(d, Ah[0], Ah[1], Ah[2], Ah[3], Bh0, Bh1);
        mma16(d, Ah[0], Ah[1], Ah[2], Ah[3], Bl0, Bl1);
        mma16(d, Al[0], Al[1], Al[2], Al[3], Bh0, Bh1);

        float* op = out + ((size_t)(b * SS + s0 + sw + gid)) * DOUT
                        + o0 + ow + nt * 8 + tig * 2;
        *(float2*)op = make_float2(d[0], d[1]);
        *(float2*)(op + (size_t)8 * DOUT) = make_float2(d[2], d[3]);
    }
}

// ---------------------------------------------------------------------------
extern "C" void kernel_launch(void* const* d_in, const int* in_sizes, int n_in,
                              void* d_out, int out_size) {
    const float* h     = (const float*)d_in[0];   // [8,2048,2048]
    const float* alpha = (const float*)d_in[1];   // [8,16]
    const float* Abank = (const float*)d_in[2];   // [16,16,2048]
    const float* Bbank = (const float*)d_in[3];   // [16,2048,16]
    float* out = (float*)d_out;                   // [8,2048,2048]

    static bool attr_set = false;
    if (!attr_set) {
        cudaFuncSetAttribute(z_mma_kernel,
                             cudaFuncAttributeMaxDynamicSharedMemorySize,
                             Z_SMEM_BYTES);
        attr_set = true;
    }

    mix_kernel<<<256, 256>>>(alpha, Abank, Bbank);
    z_mma_kernel<<<256, 256, Z_SMEM_BYTES>>>(h);
    delta_kernel<<<2048, 512>>>(out);
}

// round 16
// speedup vs baseline: 1.2030x; 1.0035x over previous
#include <cuda_runtime.h>
#include <cuda_bf16.h>
#include <cstdint>

#define BB    8
#define SS    2048
#define DIN   2048
#define DOUT  2048
#define KK    16
#define RR    16

// Pre-split bf16 hi/lo mixed weights (u32 = packed bf16 pair over last dim),
// plus K-split z partials.
__device__ __align__(16) uint32_t g_Amh[BB * RR * DIN / 2];    // [b][r][i/2]
__device__ __align__(16) uint32_t g_Aml[BB * RR * DIN / 2];
__device__ __align__(16) uint32_t g_BmTh[BB * DOUT * RR / 2];  // [b][o][r/2]
__device__ __align__(16) uint32_t g_BmTl[BB * DOUT * RR / 2];
__device__ __align__(16) float    g_zp[2 * BB * SS * RR];      // [kh][b][s][r]

// z smem buffer layout (u32 words): hs_hi[4608] hs_lo[4608] as_hi[768] as_lo[768]
#define ZB_HSLO 4608
#define ZB_ASHI 9216
#define ZB_ASLO 9984
#define ZB_SIZE 10752            // words per buffer
#define Z_SMEM_BYTES (2 * ZB_SIZE * 4)   // 86016 -> occ 2 (172 KB < 228 KB)

// ---------------------------------------------------------------------------
__device__ __forceinline__ void split2(float x, float y, uint32_t &hi, uint32_t &lo) {
    __nv_bfloat162 h2 = __floats2bfloat162_rn(x, y);
    float rx = x - __bfloat162float(h2.x);
    float ry = y - __bfloat162float(h2.y);
    __nv_bfloat162 l2 = __floats2bfloat162_rn(rx, ry);
    hi = *reinterpret_cast<uint32_t*>(&h2);
    lo = *reinterpret_cast<uint32_t*>(&l2);
}

__device__ __forceinline__ void pack4(float4 v, uint2 &hi, uint2 &lo) {
    split2(v.x, v.y, hi.x, lo.x);
    split2(v.z, v.w, hi.y, lo.y);
}

// m16n8k16 bf16 mma, fp32 accumulate.
__device__ __forceinline__ void mma16(float* d,
                                      uint32_t a0, uint32_t a1, uint32_t a2, uint32_t a3,
                                      uint32_t b0, uint32_t b1) {
    asm("mma.sync.aligned.m16n8k16.row.col.f32.bf16.bf16.f32 "
        "{%0,%1,%2,%3}, {%4,%5,%6,%7}, {%8,%9}, {%0,%1,%2,%3};"
        : "+f"(d[0]), "+f"(d[1]), "+f"(d[2]), "+f"(d[3])
        : "r"(a0), "r"(a1), "r"(a2), "r"(a3), "r"(b0), "r"(b1));
}

// ---------------------------------------------------------------------------
// Kernel 1: mix banks -> pre-split bf16 hi/lo (coalesced B part). Unchanged.
// ---------------------------------------------------------------------------
__global__ void __launch_bounds__(256, 2) mix_kernel(const float* __restrict__ alpha,
                                                     const float* __restrict__ Abank,
                                                     const float* __restrict__ Bbank) {
    __shared__ float sal[BB * KK];
    if (threadIdx.x < BB * KK) sal[threadIdx.x] = alpha[threadIdx.x];
    __syncthreads();

    int t = blockIdx.x * blockDim.x + threadIdx.x;
    if (t < 32768) {
        int bg  = t >> 13;
        int rem = t & 8191;
        int r   = rem >> 9;
        int i   = (rem & 511) << 2;
        const float* ab = Abank + (size_t)r * DIN + i;
        float4 a0 = make_float4(0.f, 0.f, 0.f, 0.f);
        float4 a1 = a0;
#pragma unroll
        for (int k = 0; k < KK; k++) {
            float4 v = *(const float4*)(ab + (size_t)k * RR * DIN);
            float c0 = sal[(2 * bg) * KK + k];
            float c1 = sal[(2 * bg + 1) * KK + k];
            a0.x += c0 * v.x; a0.y += c0 * v.y; a0.z += c0 * v.z; a0.w += c0 * v.w;
            a1.x += c1 * v.x; a1.y += c1 * v.y; a1.z += c1 * v.z; a1.w += c1 * v.w;
        }
        uint2 hi, lo;
        size_t idx0 = (size_t)((2 * bg) * RR + r) * (DIN / 2) + (i >> 1);
        pack4(a0, hi, lo);
        *(uint2*)&g_Amh[idx0] = hi;  *(uint2*)&g_Aml[idx0] = lo;
        size_t idx1 = (size_t)((2 * bg + 1) * RR + r) * (DIN / 2) + (i >> 1);
        pack4(a1, hi, lo);
        *(uint2*)&g_Amh[idx1] = hi;  *(uint2*)&g_Aml[idx1] = lo;
    } else {
        int t2  = t - 32768;
        int bg  = t2 >> 13;
        int rem = t2 & 8191;
        int o   = rem >> 2;
        int q   = rem & 3;
        const float* bb = Bbank + (size_t)o * RR + 4 * q;
        float4 a0 = make_float4(0.f, 0.f, 0.f, 0.f);
        float4 a1 = a0;
#pragma unroll
        for (int k = 0; k < KK; k++) {
            float4 v = *(const float4*)(bb + (size_t)k * DOUT * RR);
            float c0 = sal[(2 * bg) * KK + k];
            float c1 = sal[(2 * bg + 1) * KK + k];
            a0.x += c0 * v.x; a0.y += c0 * v.y; a0.z += c0 * v.z; a0.w += c0 * v.w;
            a1.x += c1 * v.x; a1.y += c1 * v.y; a1.z += c1 * v.z; a1.w += c1 * v.w;
        }
        uint2 hi, lo;
        size_t idx0 = (size_t)((2 * bg) * DOUT + o) * (RR / 2) + 2 * q;
        pack4(a0, hi, lo);
        *(uint2*)&g_BmTh[idx0] = hi;  *(uint2*)&g_BmTl[idx0] = lo;
        size_t idx1 = (size_t)((2 * bg + 1) * DOUT + o) * (RR / 2) + 2 * q;
        pack4(a1, hi, lo);
        *(uint2*)&g_BmTh[idx1] = hi;  *(uint2*)&g_BmTl[idx1] = lo;
    }
}

// ---------------------------------------------------------------------------
// Kernel 2: z partials, double-buffered pipeline (R15 base).
// CHANGE vs R15: SEPARATE accumulators per split term (hh/hl/lh) -> 6
// independent mma dependency chains per warp instead of 2; merged in epilogue.
// ---------------------------------------------------------------------------
__global__ void __launch_bounds__(256, 2) z_mma_kernel(const float* __restrict__ h) {
    extern __shared__ uint32_t zsm[];
    uint32_t* const buf0 = zsm;
    uint32_t* const buf1 = zsm + ZB_SIZE;

    int kh = blockIdx.x & 1;
    int st = (blockIdx.x >> 1) & 15;
    int b  = blockIdx.x >> 5;
    int s0 = st * 128;
    int ibase = kh * (DIN / 4);   // u32 columns per K-half = 512

    int tid  = threadIdx.x;
    int w    = tid >> 5;
    int lane = tid & 31;
    int gid  = lane >> 2;
    int tig  = lane & 3;

    int row16 = tid >> 4;
    int col   = tid & 15;

    const uint32_t* amh = g_Amh + (size_t)b * RR * (DIN / 2);
    const uint32_t* aml = g_Aml + (size_t)b * RR * (DIN / 2);
    const float*    hb  = h + (size_t)(b * SS + s0 + row16) * DIN + col * 4;

    // d[nt][split][4]: split 0=hh, 1=hl, 2=lh — independent chains.
    float d[2][3][4];
#pragma unroll
    for (int nt = 0; nt < 2; nt++)
#pragma unroll
        for (int sp = 0; sp < 3; sp++)
#pragma unroll
            for (int j = 0; j < 4; j++) d[nt][sp][j] = 0.f;

    float4 v[8];
    uint32_t ar_hi[2], ar_lo[2];

    // ---- load chunk 0 regs (coalesced Am gather: warp per r-row) ----
    {
        int icol0 = ibase;
#pragma unroll
        for (int p = 0; p < 8; p++)
            v[p] = *(const float4*)(hb + (size_t)(p * 16) * DIN + 2 * icol0);
#pragma unroll
        for (int p = 0; p < 2; p++) {
            size_t gidx = (size_t)(w + 8 * p) * (DIN / 2) + icol0 + lane;
            ar_hi[p] = amh[gidx];
            ar_lo[p] = aml[gidx];
        }
    }
    // ---- stage chunk 0 -> buf0 ----
    {
        uint32_t* hsh = buf0;
        uint32_t* hsl = buf0 + ZB_HSLO;
#pragma unroll
        for (int p = 0; p < 8; p++) {
            uint32_t h01, l01, h23, l23;
            split2(v[p].x, v[p].y, h01, l01);
            split2(v[p].z, v[p].w, h23, l23);
            int base = (p * 16 + row16) * 36 + col * 2;
            hsh[base] = h01;  hsh[base + 1] = h23;
            hsl[base] = l01;  hsl[base + 1] = l23;
        }
        uint32_t* ash = buf0 + ZB_ASHI;
        uint32_t* asl = buf0 + ZB_ASLO;
#pragma unroll
        for (int p = 0; p < 2; p++) {
            ash[lane * 24 + (w + 8 * p)] = ar_hi[p];
            asl[lane * 24 + (w + 8 * p)] = ar_lo[p];
        }
    }
    __syncthreads();

    // ---- prefetch chunk 1 regs ----
    {
        int icol1 = ibase + 32;
#pragma unroll
        for (int p = 0; p < 8; p++)
            v[p] = *(const float4*)(hb + (size_t)(p * 16) * DIN + 2 * icol1);
#pragma unroll
        for (int p = 0; p < 2; p++) {
            size_t gidx = (size_t)(w + 8 * p) * (DIN / 2) + icol1 + lane;
            ar_hi[p] = amh[gidx];
            ar_lo[p] = aml[gidx];
        }
    }

#pragma unroll 1
    for (int c = 0; c < 16; c++) {
        uint32_t* cur = (c & 1) ? buf1 : buf0;
        uint32_t* nxt = (c & 1) ? buf0 : buf1;

        // ---- stage chunk c+1 into nxt (regs already loaded) ----
        if (c < 15) {
            uint32_t* hsh = nxt;
            uint32_t* hsl = nxt + ZB_HSLO;
#pragma unroll
            for (int p = 0; p < 8; p++) {
                uint32_t h01, l01, h23, l23;
                split2(v[p].x, v[p].y, h01, l01);
                split2(v[p].z, v[p].w, h23, l23);
                int base = (p * 16 + row16) * 36 + col * 2;
                hsh[base] = h01;  hsh[base + 1] = h23;
                hsl[base] = l01;  hsl[base + 1] = l23;
            }
            uint32_t* ash = nxt + ZB_ASHI;
            uint32_t* asl = nxt + ZB_ASLO;
#pragma unroll
            for (int p = 0; p < 2; p++) {
                ash[lane * 24 + (w + 8 * p)] = ar_hi[p];
                asl[lane * 24 + (w + 8 * p)] = ar_lo[p];
            }
        }

        // ---- prefetch chunk c+2 regs (v dead after staging) ----
        if (c < 14) {
            int icoln = ibase + (c + 2) * 32;
#pragma unroll
            for (int p = 0; p < 8; p++)
                v[p] = *(const float4*)(hb + (size_t)(p * 16) * DIN + 2 * icoln);
#pragma unroll
            for (int p = 0; p < 2; p++) {
                size_t gidx = (size_t)(w + 8 * p) * (DIN / 2) + icoln + lane;
                ar_hi[p] = amh[gidx];
                ar_lo[p] = aml[gidx];
            }
        }

        // ---- compute chunk c from cur: 4 k16 steps, 6 independent chains ----
        {
            const uint32_t* hsh = cur;
            const uint32_t* hsl = cur + ZB_HSLO;
            const uint32_t* ash = cur + ZB_ASHI;
            const uint32_t* asl = cur + ZB_ASLO;
#pragma unroll
            for (int km = 0; km < 4; km++) {
                int ac0 = (km * 8 + tig) * 24;
                int ac1 = (km * 8 + 4 + tig) * 24;
                uint32_t Ah0 = ash[ac0 + gid], Ah1 = ash[ac0 + gid + 8];
                uint32_t Ah2 = ash[ac1 + gid], Ah3 = ash[ac1 + gid + 8];
                uint32_t Al0 = asl[ac0 + gid], Al1 = asl[ac0 + gid + 8];
                uint32_t Al2 = asl[ac1 + gid], Al3 = asl[ac1 + gid + 8];
#pragma unroll
                for (int nt = 0; nt < 2; nt++) {
                    int srow = (w * 16 + nt * 8 + gid) * 36 + km * 8 + tig;
                    uint32_t Bh0 = hsh[srow], Bh1 = hsh[srow + 4];
                    uint32_t Bl0 = hsl[srow], Bl1 = hsl[srow + 4];
                    mma16(d[nt][0], Ah0, Ah1, Ah2, Ah3, Bh0, Bh1);   // hh
                    mma16(d[nt][1], Ah0, Ah1, Ah2, Ah3, Bl0, Bl1);   // hl
                    mma16(d[nt][2], Al0, Al1, Al2, Al3, Bh0, Bh1);   // lh
                }
            }
        }
        __syncthreads();   // nxt fully staged; cur free for re-staging
    }

    // Epilogue: merge split chains, then write.
    float* zp = g_zp + ((size_t)(kh * BB + b) * SS) * RR;
#pragma unroll
    for (int nt = 0; nt < 2; nt++) {
        float m0 = d[nt][0][0] + d[nt][1][0] + d[nt][2][0];
        float m1 = d[nt][0][1] + d[nt][1][1] + d[nt][2][1];
        float m2 = d[nt][0][2] + d[nt][1][2] + d[nt][2][2];
        float m3 = d[nt][0][3] + d[nt][1][3] + d[nt][2][3];
        int sbase = s0 + w * 16 + nt * 8 + 2 * tig;
        zp[(size_t)sbase * RR + gid]           = m0;
        zp[(size_t)(sbase + 1) * RR + gid]     = m1;
        zp[(size_t)sbase * RR + gid + 8]       = m2;
        zp[(size_t)(sbase + 1) * RR + gid + 8] = m3;
    }
}

// ---------------------------------------------------------------------------
// Kernel 3: delta[b][s][o] = sum_r z[b][s][r] * BmT[b][o][r]
// m16n8k16: 3 mma per 16x8 tile. Unchanged (at its floor). 2048 CTAs, 512 thr.
// ---------------------------------------------------------------------------
__global__ void __launch_bounds__(512, 2) delta_kernel(float* __restrict__ out) {
    __shared__ float zs[128 * 20];
    __shared__ uint32_t bsh[128 * 9];
    __shared__ uint32_t bsl[128 * 9];

    int ot = blockIdx.x & 15;
    int st = (blockIdx.x >> 4) & 15;
    int b  = blockIdx.x >> 8;
    int s0 = st * 128;
    int o0 = ot * 128;
    int tid = threadIdx.x;

    {
        int row = tid >> 2;
        int col = (tid & 3) << 2;
        size_t src = ((size_t)(b * SS) + s0 + row) * RR + col;
        float4 p0 = *(const float4*)(g_zp + src);
        float4 p1 = *(const float4*)(g_zp + (size_t)BB * SS * RR + src);
        *(float4*)(zs + row * 20 + col) =
            make_float4(p0.x + p1.x, p0.y + p1.y, p0.z + p1.z, p0.w + p1.w);
    }
    {
        size_t base = (size_t)(b * DOUT + o0) * (RR / 2);
#pragma unroll
        for (int j = 0; j < 2; j++) {
            int idx = tid * 2 + j;
            int row = idx >> 3;
            int col = idx & 7;
            bsh[row * 9 + col] = g_BmTh[base + idx];
            bsl[row * 9 + col] = g_BmTl[base + idx];
        }
    }
    __syncthreads();

    int w = tid >> 5;
    int lane = tid & 31;
    int gid = lane >> 2;
    int tig = lane & 3;
    int sw = (w & 7) * 16;
    int ow = (w >> 3) * 64;

    uint32_t Ah[4], Al[4];
#pragma unroll
    for (int kk = 0; kk < 2; kk++) {
        float2 v0 = *(const float2*)(zs + (sw + gid) * 20 + kk * 8 + tig * 2);
        float2 v1 = *(const float2*)(zs + (sw + gid + 8) * 20 + kk * 8 + tig * 2);
        split2(v0.x, v0.y, Ah[2 * kk],     Al[2 * kk]);
        split2(v1.x, v1.y, Ah[2 * kk + 1], Al[2 * kk + 1]);
    }

#pragma unroll
    for (int nt = 0; nt < 8; nt++) {
        int brow = (ow + nt * 8 + gid) * 9;
        uint32_t Bh0 = bsh[brow + tig];
        uint32_t Bh1 = bsh[brow + 4 + tig];
        uint32_t Bl0 = bsl[brow + tig];
        uint32_t Bl1 = bsl[brow + 4 + tig];

        float d[4] = {0.f, 0.f, 0.f, 0.f};
        mma16(d, Ah[0], Ah[1], Ah[2], Ah[3], Bh0, Bh1);
        mma16(d, Ah[0], Ah[1], Ah[2], Ah[3], Bl0, Bl1);
        mma16(d, Al[0], Al[1], Al[2], Al[3], Bh0, Bh1);

        float* op = out + ((size_t)(b * SS + s0 + sw + gid)) * DOUT
                        + o0 + ow + nt * 8 + tig * 2;
        *(float2*)op = make_float2(d[0], d[1]);
        *(float2*)(op + (size_t)8 * DOUT) = make_float2(d[2], d[3]);
    }
}

// ---------------------------------------------------------------------------
extern "C" void kernel_launch(void* const* d_in, const int* in_sizes, int n_in,
                              void* d_out, int out_size) {
    const float* h     = (const float*)d_in[0];   // [8,2048,2048]
    const float* alpha = (const float*)d_in[1];   // [8,16]
    const float* Abank = (const float*)d_in[2];   // [16,16,2048]
    const float* Bbank = (const float*)d_in[3];   // [16,2048,16]
    float* out = (float*)d_out;                   // [8,2048,2048]

    static bool attr_set = false;
    if (!attr_set) {
        cudaFuncSetAttribute(z_mma_kernel,
                             cudaFuncAttributeMaxDynamicSharedMemorySize,
                             Z_SMEM_BYTES);
        attr_set = true;
    }

    mix_kernel<<<256, 256>>>(alpha, Abank, Bbank);
    z_mma_kernel<<<256, 256, Z_SMEM_BYTES>>>(h);
    delta_kernel<<<2048, 512>>>(out);
}